// round 5
// baseline (speedup 1.0000x reference)
#include <cuda_runtime.h>
#include <cuda_bf16.h>
#include <math.h>
#include <stdint.h>

#define D_MODEL 1024
#define N_HEAD  16
#define BB      2
#define TT      2048
#define ROWS    (BB*TT)      // 4096
#define EXPAND  4

// ---------------- scratch (device globals; no allocation allowed) ----------
__device__ __nv_bfloat16 g_ahi[ROWS * D_MODEL];
__device__ __nv_bfloat16 g_alo[ROWS * D_MODEL];
__device__ __nv_bfloat16 g_bhi[ROWS * EXPAND * D_MODEL];   // also holds qkv pair
__device__ __nv_bfloat16 g_blo[ROWS * EXPAND * D_MODEL];
__device__ __nv_bfloat16 g_whi[EXPAND * D_MODEL * D_MODEL];
__device__ __nv_bfloat16 g_wlo[EXPAND * D_MODEL * D_MODEL];
__device__ float g_x1 [ROWS * D_MODEL];

// ================= helpers ==================================================
__device__ __forceinline__ uint32_t smem_to_u32(const void* p) {
    uint32_t a;
    asm("{ .reg .u64 t; cvta.to.shared.u64 t, %1; cvt.u32.u64 %0, t; }" : "=r"(a) : "l"(p));
    return a;
}
#define SMEM_SWIZZLE_128B(off) ((off) ^ (((off) >> 3) & 0x70))

#define CP_ASYNC16(dst_u32, src_ptr) \
    asm volatile("cp.async.cg.shared.global [%0], [%1], 16;" :: "r"(dst_u32), "l"(src_ptr))
#define CP_COMMIT() asm volatile("cp.async.commit_group;" ::: "memory")
#define CP_WAIT0()  asm volatile("cp.async.wait_group 0;" ::: "memory")
#define CP_WAIT1()  asm volatile("cp.async.wait_group 1;" ::: "memory")

#define LDMATRIX_X4(r0, r1, r2, r3, addr) \
    asm volatile("ldmatrix.sync.aligned.m8n8.x4.shared.b16 {%0,%1,%2,%3}, [%4];" \
        : "=r"(r0), "=r"(r1), "=r"(r2), "=r"(r3) : "r"(addr))
#define LDMATRIX_X4_TRANS(r0, r1, r2, r3, addr) \
    asm volatile("ldmatrix.sync.aligned.m8n8.x4.trans.shared.b16 {%0,%1,%2,%3}, [%4];" \
        : "=r"(r0), "=r"(r1), "=r"(r2), "=r"(r3) : "r"(addr))

__device__ __forceinline__ void hmma(float* c, const uint32_t* a, const uint32_t* b) {
    asm volatile(
        "mma.sync.aligned.m16n8k16.row.col.f32.bf16.bf16.f32 "
        "{%0,%1,%2,%3}, {%4,%5,%6,%7}, {%8,%9}, {%0,%1,%2,%3};"
        : "+f"(c[0]), "+f"(c[1]), "+f"(c[2]), "+f"(c[3])
        : "r"(a[0]), "r"(a[1]), "r"(a[2]), "r"(a[3]), "r"(b[0]), "r"(b[1]));
}

__device__ __forceinline__ void split_bf16(float v, __nv_bfloat16& hi, __nv_bfloat16& lo) {
    hi = __float2bfloat16(v);
    lo = __float2bfloat16(v - __bfloat162float(hi));
}

// ---------------- LayerNorm -> bf16 hi/lo pair -------------------------------
__global__ __launch_bounds__(256)
void ln_kernel(const float* __restrict__ x, const float* __restrict__ w,
               const float* __restrict__ b,
               __nv_bfloat16* __restrict__ ohi, __nv_bfloat16* __restrict__ olo) {
    int row = blockIdx.x;
    const float4* xr = (const float4*)(x + (size_t)row * D_MODEL);
    float4 v = xr[threadIdx.x];
    float s  = v.x + v.y + v.z + v.w;
    float ss = v.x*v.x + v.y*v.y + v.z*v.z + v.w*v.w;
    #pragma unroll
    for (int o = 16; o; o >>= 1) {
        s  += __shfl_down_sync(0xffffffffu, s,  o);
        ss += __shfl_down_sync(0xffffffffu, ss, o);
    }
    __shared__ float rs[8], rss[8];
    __shared__ float mu_s, rstd_s;
    int wid = threadIdx.x >> 5, lid = threadIdx.x & 31;
    if (lid == 0) { rs[wid] = s; rss[wid] = ss; }
    __syncthreads();
    if (threadIdx.x == 0) {
        float ts = 0.f, tss = 0.f;
        #pragma unroll
        for (int i = 0; i < 8; i++) { ts += rs[i]; tss += rss[i]; }
        float mu  = ts * (1.0f / D_MODEL);
        float var = tss * (1.0f / D_MODEL) - mu * mu;
        mu_s = mu; rstd_s = rsqrtf(var + 1e-5f);
    }
    __syncthreads();
    float mu = mu_s, rstd = rstd_s;
    float4 wv = ((const float4*)w)[threadIdx.x];
    float4 bv = ((const float4*)b)[threadIdx.x];
    float o0 = (v.x - mu) * rstd * wv.x + bv.x;
    float o1 = (v.y - mu) * rstd * wv.y + bv.y;
    float o2 = (v.z - mu) * rstd * wv.z + bv.z;
    float o3 = (v.w - mu) * rstd * wv.w + bv.w;
    size_t base = (size_t)row * D_MODEL + threadIdx.x * 4;
    __nv_bfloat16 h, l;
    split_bf16(o0, h, l); ohi[base+0] = h; olo[base+0] = l;
    split_bf16(o1, h, l); ohi[base+1] = h; olo[base+1] = l;
    split_bf16(o2, h, l); ohi[base+2] = h; olo[base+2] = l;
    split_bf16(o3, h, l); ohi[base+3] = h; olo[base+3] = l;
}

// ---------------- weight transpose + split: W[K,N] -> Wt[N,K] ---------------
__global__ __launch_bounds__(256)
void wtrans_kernel(const float* __restrict__ W,
                   __nv_bfloat16* __restrict__ whi, __nv_bfloat16* __restrict__ wlo,
                   int K, int N) {
    __shared__ float t[32][33];
    int n0 = blockIdx.x * 32, k0 = blockIdx.y * 32;
    int tx = threadIdx.x & 31, ty = threadIdx.x >> 5;
    #pragma unroll
    for (int i = 0; i < 32; i += 8)
        t[ty + i][tx] = W[(size_t)(k0 + ty + i) * N + n0 + tx];
    __syncthreads();
    #pragma unroll
    for (int i = 0; i < 32; i += 8) {
        float v = t[tx][ty + i];
        __nv_bfloat16 h, l;
        split_bf16(v, h, l);
        size_t o = (size_t)(n0 + ty + i) * K + k0 + tx;
        whi[o] = h; wlo[o] = l;
    }
}

// ---------------- bf16x3 HMMA GEMM: C = (Ahi+Alo) @ (Bhi+Blo)^T -------------
// CTA tile 256x128, BK=64, 8 warps each 64x64.
// EPI: 0 bias -> f32 C; 1 bias+residual -> f32 C; 2 bias+GELU -> bf16 pair;
//      3 bias -> bf16 pair
#define GEMM_STAGE_BYTES 98304           // A pair 64KB + B pair 32KB
#define GEMM_SMEM_BYTES (2 * GEMM_STAGE_BYTES)

template<int EPI>
__global__ __launch_bounds__(256, 1)
void gemm_tc(const __nv_bfloat16* __restrict__ Ahi, const __nv_bfloat16* __restrict__ Alo,
             const __nv_bfloat16* __restrict__ Bhi, const __nv_bfloat16* __restrict__ Blo,
             const float* __restrict__ bias, const float* __restrict__ res,
             float* __restrict__ C,
             __nv_bfloat16* __restrict__ Chi, __nv_bfloat16* __restrict__ Clo,
             int M, int N, int K) {
    extern __shared__ __align__(128) char smem[];
    uint32_t su = smem_to_u32(smem);

    const int tid  = threadIdx.x;
    const int lane = tid & 31;
    const int wid  = tid >> 5;
    const int wm   = (wid & 3) * 64;    // 4 warps along M (256)
    const int wn   = (wid >> 2) * 64;   // 2 warps along N (128)
    const int m0 = blockIdx.y * 256, n0 = blockIdx.x * 128;

    float acc[4][8][4];
    #pragma unroll
    for (int i = 0; i < 4; i++)
        #pragma unroll
        for (int j = 0; j < 8; j++)
            #pragma unroll
            for (int k = 0; k < 4; k++) acc[i][j][k] = 0.f;

    const int nkt = K >> 6;
    const int lrow16 = lane & 15;
    const int khalf  = (lane >> 4) << 4;

    auto issue_loads = [&](int kt, int s) {
        uint32_t base = su + s * GEMM_STAGE_BYTES;
        int k0 = kt << 6;
        #pragma unroll
        for (int j = 0; j < 8; j++) {          // A pair: 256 rows x 128B
            int e = j * 256 + tid;
            int r = e >> 3, c = e & 7;
            uint32_t d = SMEM_SWIZZLE_128B((uint32_t)(r * 128 + c * 16));
            size_t asrc = (size_t)(m0 + r) * K + k0 + c * 8;
            CP_ASYNC16(base + d,         Ahi + asrc);
            CP_ASYNC16(base + 32768 + d, Alo + asrc);
        }
        #pragma unroll
        for (int j = 0; j < 4; j++) {          // B pair: 128 rows x 128B
            int e = j * 256 + tid;
            int r = e >> 3, c = e & 7;
            uint32_t d = SMEM_SWIZZLE_128B((uint32_t)(r * 128 + c * 16));
            size_t bsrc = (size_t)(n0 + r) * K + k0 + c * 8;
            CP_ASYNC16(base + 65536 + d, Bhi + bsrc);
            CP_ASYNC16(base + 81920 + d, Blo + bsrc);
        }
        CP_COMMIT();
    };

    issue_loads(0, 0);

    for (int kt = 0; kt < nkt; kt++) {
        int s = kt & 1;
        if (kt + 1 < nkt) { issue_loads(kt + 1, s ^ 1); CP_WAIT1(); }
        else              { CP_WAIT0(); }
        __syncthreads();

        uint32_t base = su + s * GEMM_STAGE_BYTES;
        #pragma unroll
        for (int ks = 0; ks < 4; ks++) {
            const uint32_t kb = (uint32_t)(ks * 32 + khalf);
            uint32_t ah[4][4], al[4][4];
            #pragma unroll
            for (int mt = 0; mt < 4; mt++) {
                int r = wm + mt * 16 + lrow16;
                uint32_t off = (uint32_t)(r * 128) + (kb ^ (uint32_t)((r & 7) << 4));
                LDMATRIX_X4(ah[mt][0], ah[mt][1], ah[mt][2], ah[mt][3], base + off);
                LDMATRIX_X4(al[mt][0], al[mt][1], al[mt][2], al[mt][3], base + 32768 + off);
            }
            uint32_t bh[8][2], bl[8][2];
            #pragma unroll
            for (int p = 0; p < 4; p++) {
                int r = wn + p * 16 + lrow16;
                uint32_t off = (uint32_t)(r * 128) + (kb ^ (uint32_t)((r & 7) << 4));
                uint32_t r0, r1, r2, r3;
                LDMATRIX_X4(r0, r1, r2, r3, base + 65536 + off);
                bh[p*2][0] = r0; bh[p*2][1] = r2;
                bh[p*2+1][0] = r1; bh[p*2+1][1] = r3;
                LDMATRIX_X4(r0, r1, r2, r3, base + 81920 + off);
                bl[p*2][0] = r0; bl[p*2][1] = r2;
                bl[p*2+1][0] = r1; bl[p*2+1][1] = r3;
            }
            #pragma unroll
            for (int mt = 0; mt < 4; mt++)
                #pragma unroll
                for (int nt = 0; nt < 8; nt++) {
                    hmma(acc[mt][nt], ah[mt], bh[nt]);
                    hmma(acc[mt][nt], ah[mt], bl[nt]);
                    hmma(acc[mt][nt], al[mt], bh[nt]);
                }
        }
        __syncthreads();
    }

    const int rbase = m0 + wm + (lane >> 2);
    const int cbase = n0 + wn + (lane & 3) * 2;
    #pragma unroll
    for (int mt = 0; mt < 4; mt++) {
        #pragma unroll
        for (int nt = 0; nt < 8; nt++) {
            int col = cbase + nt * 8;
            float b0 = bias[col], b1 = bias[col + 1];
            #pragma unroll
            for (int half = 0; half < 2; half++) {
                int row = rbase + mt * 16 + half * 8;
                float v0 = acc[mt][nt][half * 2]     + b0;
                float v1 = acc[mt][nt][half * 2 + 1] + b1;
                if (EPI == 1) {
                    float2 rv = *(const float2*)(res + (size_t)row * N + col);
                    v0 += rv.x; v1 += rv.y;
                }
                if (EPI == 2) {
                    v0 = 0.5f * v0 * (1.0f + erff(v0 * 0.70710678118654752f));
                    v1 = 0.5f * v1 * (1.0f + erff(v1 * 0.70710678118654752f));
                }
                if (EPI >= 2) {
                    __nv_bfloat16 h0, l0, h1, l1;
                    split_bf16(v0, h0, l0);
                    split_bf16(v1, h1, l1);
                    __nv_bfloat162 hp; hp.x = h0; hp.y = h1;
                    __nv_bfloat162 lp; lp.x = l0; lp.y = l1;
                    *(__nv_bfloat162*)(Chi + (size_t)row * N + col) = hp;
                    *(__nv_bfloat162*)(Clo + (size_t)row * N + col) = lp;
                } else {
                    float2 o; o.x = v0; o.y = v1;
                    *(float2*)(C + (size_t)row * N + col) = o;
                }
            }
        }
    }
}

// ---------------- tensor-core flash attention --------------------------------
#define ATTN_SMEM (32768 + 2 * 32768)   // Q pair + 2 KV stages

__global__ __launch_bounds__(128, 1)
void attn_tc(const __nv_bfloat16* __restrict__ qh, const __nv_bfloat16* __restrict__ ql,
             __nv_bfloat16* __restrict__ yhi, __nv_bfloat16* __restrict__ ylo) {
    extern __shared__ __align__(128) char smem[];
    uint32_t su = smem_to_u32(smem);
    const int tid = threadIdx.x, lane = tid & 31, w = tid >> 5;
    const int bh = blockIdx.y, b = bh >> 4, h = bh & 15;
    const int qt = (int)gridDim.x - 1 - (int)blockIdx.x;
    const int ntiles = qt * 2 + 2;

    const uint32_t QH = su, QL = su + 16384;
    const size_t qrow0 = (size_t)(b * TT + qt * 128);

    #pragma unroll
    for (int j = 0; j < 8; j++) {
        int e = j * 128 + tid; int r = e >> 3, c = e & 7;
        uint32_t d = SMEM_SWIZZLE_128B((uint32_t)(r * 128 + c * 16));
        size_t src = (qrow0 + r) * (3 * D_MODEL) + h * 64 + c * 8;
        CP_ASYNC16(QH + d, qh + src);
        CP_ASYNC16(QL + d, ql + src);
    }
    auto issue_kv = [&](int kt, int s) {
        uint32_t base = su + 32768 + s * 32768;
        size_t krow0 = (size_t)(b * TT + kt * 64);
        #pragma unroll
        for (int j = 0; j < 4; j++) {
            int e = j * 128 + tid; int r = e >> 3, c = e & 7;
            uint32_t d = SMEM_SWIZZLE_128B((uint32_t)(r * 128 + c * 16));
            size_t ksrc = (krow0 + r) * (3 * D_MODEL) + D_MODEL + h * 64 + c * 8;
            size_t vsrc = ksrc + D_MODEL;
            CP_ASYNC16(base +         d, qh + ksrc);
            CP_ASYNC16(base +  8192 + d, ql + ksrc);
            CP_ASYNC16(base + 16384 + d, qh + vsrc);
            CP_ASYNC16(base + 24576 + d, ql + vsrc);
        }
        CP_COMMIT();
    };
    issue_kv(0, 0);

    float O[2][8][4];
    #pragma unroll
    for (int mt = 0; mt < 2; mt++)
        #pragma unroll
        for (int dt = 0; dt < 8; dt++)
            #pragma unroll
            for (int k = 0; k < 4; k++) O[mt][dt][k] = 0.f;
    float mrow[2][2] = {{-1e30f, -1e30f}, {-1e30f, -1e30f}};
    float lrow[2][2] = {{0.f, 0.f}, {0.f, 0.f}};

    const int lrow16 = lane & 15;
    const uint32_t khalfB = (uint32_t)((lane >> 4) << 4);
    const int r4 = lane >> 2, c2 = (lane & 3) * 2;

    for (int kt = 0; kt < ntiles; kt++) {
        int s = kt & 1;
        if (kt + 1 < ntiles) { issue_kv(kt + 1, s ^ 1); CP_WAIT1(); }
        else                 { CP_WAIT0(); }
        __syncthreads();
        const uint32_t KB = su + 32768 + s * 32768;
        const uint32_t VB = KB + 16384;

        #pragma unroll
        for (int mt = 0; mt < 2; mt++) {
            const int qmt = qt * 128 + w * 32 + mt * 16;
            float sa[8][4];
            #pragma unroll
            for (int nt = 0; nt < 8; nt++)
                #pragma unroll
                for (int k = 0; k < 4; k++) sa[nt][k] = 0.f;

            #pragma unroll
            for (int ks = 0; ks < 4; ks++) {
                const uint32_t kb = (uint32_t)(ks * 32) + khalfB;
                const int ar = w * 32 + mt * 16 + lrow16;
                uint32_t aoff = (uint32_t)(ar * 128) + (kb ^ (uint32_t)((ar & 7) << 4));
                uint32_t ah[4], al[4];
                LDMATRIX_X4(ah[0], ah[1], ah[2], ah[3], QH + aoff);
                LDMATRIX_X4(al[0], al[1], al[2], al[3], QL + aoff);
                uint32_t kh[8][2], kl[8][2];
                #pragma unroll
                for (int p = 0; p < 4; p++) {
                    const int br = p * 16 + lrow16;
                    uint32_t boff = (uint32_t)(br * 128) + (kb ^ (uint32_t)((br & 7) << 4));
                    uint32_t r0, r1, r2, r3;
                    LDMATRIX_X4(r0, r1, r2, r3, KB + boff);
                    kh[p*2][0] = r0; kh[p*2][1] = r2;
                    kh[p*2+1][0] = r1; kh[p*2+1][1] = r3;
                    LDMATRIX_X4(r0, r1, r2, r3, KB + 8192 + boff);
                    kl[p*2][0] = r0; kl[p*2][1] = r2;
                    kl[p*2+1][0] = r1; kl[p*2+1][1] = r3;
                }
                #pragma unroll
                for (int nt = 0; nt < 8; nt++) {
                    hmma(sa[nt], ah, kh[nt]);
                    hmma(sa[nt], ah, kl[nt]);
                    hmma(sa[nt], al, kh[nt]);
                }
            }

            #pragma unroll
            for (int nt = 0; nt < 8; nt++)
                #pragma unroll
                for (int k = 0; k < 4; k++) sa[nt][k] *= 0.125f;

            const int q0 = qmt + r4;
            if (kt * 64 + 63 > qmt) {
                #pragma unroll
                for (int nt = 0; nt < 8; nt++) {
                    int kv0 = kt * 64 + nt * 8 + c2;
                    if (kv0     > q0)     sa[nt][0] = -1e30f;
                    if (kv0 + 1 > q0)     sa[nt][1] = -1e30f;
                    if (kv0     > q0 + 8) sa[nt][2] = -1e30f;
                    if (kv0 + 1 > q0 + 8) sa[nt][3] = -1e30f;
                }
            }

            float tm0 = -1e30f, tm1 = -1e30f;
            #pragma unroll
            for (int nt = 0; nt < 8; nt++) {
                tm0 = fmaxf(tm0, fmaxf(sa[nt][0], sa[nt][1]));
                tm1 = fmaxf(tm1, fmaxf(sa[nt][2], sa[nt][3]));
            }
            tm0 = fmaxf(tm0, __shfl_xor_sync(0xffffffffu, tm0, 1));
            tm0 = fmaxf(tm0, __shfl_xor_sync(0xffffffffu, tm0, 2));
            tm1 = fmaxf(tm1, __shfl_xor_sync(0xffffffffu, tm1, 1));
            tm1 = fmaxf(tm1, __shfl_xor_sync(0xffffffffu, tm1, 2));
            float nm0 = fmaxf(mrow[mt][0], tm0), nm1 = fmaxf(mrow[mt][1], tm1);
            float cor0 = __expf(mrow[mt][0] - nm0), cor1 = __expf(mrow[mt][1] - nm1);
            mrow[mt][0] = nm0; mrow[mt][1] = nm1;

            float ps0 = 0.f, ps1 = 0.f;
            uint32_t Ph[8][2], Pl[8][2];
            #pragma unroll
            for (int nt = 0; nt < 8; nt++) {
                float p00 = __expf(sa[nt][0] - nm0), p01 = __expf(sa[nt][1] - nm0);
                float p10 = __expf(sa[nt][2] - nm1), p11 = __expf(sa[nt][3] - nm1);
                ps0 += p00 + p01; ps1 += p10 + p11;
                __nv_bfloat16 h0, l0, h1, l1;
                split_bf16(p00, h0, l0); split_bf16(p01, h1, l1);
                Ph[nt][0] = ((uint32_t)*(uint16_t*)&h1 << 16) | *(uint16_t*)&h0;
                Pl[nt][0] = ((uint32_t)*(uint16_t*)&l1 << 16) | *(uint16_t*)&l0;
                split_bf16(p10, h0, l0); split_bf16(p11, h1, l1);
                Ph[nt][1] = ((uint32_t)*(uint16_t*)&h1 << 16) | *(uint16_t*)&h0;
                Pl[nt][1] = ((uint32_t)*(uint16_t*)&l1 << 16) | *(uint16_t*)&l0;
            }
            ps0 += __shfl_xor_sync(0xffffffffu, ps0, 1);
            ps0 += __shfl_xor_sync(0xffffffffu, ps0, 2);
            ps1 += __shfl_xor_sync(0xffffffffu, ps1, 1);
            ps1 += __shfl_xor_sync(0xffffffffu, ps1, 2);
            lrow[mt][0] = lrow[mt][0] * cor0 + ps0;
            lrow[mt][1] = lrow[mt][1] * cor1 + ps1;

            #pragma unroll
            for (int dt = 0; dt < 8; dt++) {
                O[mt][dt][0] *= cor0; O[mt][dt][1] *= cor0;
                O[mt][dt][2] *= cor1; O[mt][dt][3] *= cor1;
            }

            #pragma unroll
            for (int ks = 0; ks < 4; ks++) {
                uint32_t vh[8][2], vl[8][2];
                #pragma unroll
                for (int dc = 0; dc < 4; dc++) {
                    const int vr = ks * 16 + lrow16;
                    uint32_t voff = (uint32_t)(vr * 128) +
                        (((uint32_t)(dc * 32) + khalfB) ^ (uint32_t)((vr & 7) << 4));
                    uint32_t r0, r1, r2, r3;
                    LDMATRIX_X4_TRANS(r0, r1, r2, r3, VB + voff);
                    vh[dc*2][0] = r0; vh[dc*2][1] = r1;
                    vh[dc*2+1][0] = r2; vh[dc*2+1][1] = r3;
                    LDMATRIX_X4_TRANS(r0, r1, r2, r3, VB + 8192 + voff);
                    vl[dc*2][0] = r0; vl[dc*2][1] = r1;
                    vl[dc*2+1][0] = r2; vl[dc*2+1][1] = r3;
                }
                uint32_t aph[4] = {Ph[2*ks][0], Ph[2*ks][1], Ph[2*ks+1][0], Ph[2*ks+1][1]};
                uint32_t apl[4] = {Pl[2*ks][0], Pl[2*ks][1], Pl[2*ks+1][0], Pl[2*ks+1][1]};
                #pragma unroll
                for (int dt = 0; dt < 8; dt++) {
                    hmma(O[mt][dt], aph, vh[dt]);
                    hmma(O[mt][dt], apl, vh[dt]);
                    hmma(O[mt][dt], aph, vl[dt]);
                }
            }
        } // mt
        __syncthreads();
    } // kt

    #pragma unroll
    for (int mt = 0; mt < 2; mt++) {
        float inv0 = 1.0f / lrow[mt][0], inv1 = 1.0f / lrow[mt][1];
        size_t row0 = qrow0 + w * 32 + mt * 16 + r4;
        size_t row1 = row0 + 8;
        #pragma unroll
        for (int dt = 0; dt < 8; dt++) {
            int col = h * 64 + dt * 8 + c2;
            float v0 = O[mt][dt][0] * inv0, v1 = O[mt][dt][1] * inv0;
            float v2 = O[mt][dt][2] * inv1, v3 = O[mt][dt][3] * inv1;
            __nv_bfloat16 h0, l0, h1, l1;
            split_bf16(v0, h0, l0); split_bf16(v1, h1, l1);
            __nv_bfloat162 hp, lp;
            hp.x = h0; hp.y = h1; lp.x = l0; lp.y = l1;
            *(__nv_bfloat162*)(yhi + row0 * D_MODEL + col) = hp;
            *(__nv_bfloat162*)(ylo + row0 * D_MODEL + col) = lp;
            split_bf16(v2, h0, l0); split_bf16(v3, h1, l1);
            hp.x = h0; hp.y = h1; lp.x = l0; lp.y = l1;
            *(__nv_bfloat162*)(yhi + row1 * D_MODEL + col) = hp;
            *(__nv_bfloat162*)(ylo + row1 * D_MODEL + col) = lp;
        }
    }
}

// ---------------- launch ----------------------------------------------------
extern "C" void kernel_launch(void* const* d_in, const int* in_sizes, int n_in,
                              void* d_out, int out_size) {
    const float* x      = (const float*)d_in[0];
    const float* ln1_w  = (const float*)d_in[1];
    const float* ln1_b  = (const float*)d_in[2];
    const float* attn_w = (const float*)d_in[3];
    const float* attn_b = (const float*)d_in[4];
    const float* proj_w = (const float*)d_in[5];
    const float* proj_b = (const float*)d_in[6];
    const float* ln2_w  = (const float*)d_in[7];
    const float* ln2_b  = (const float*)d_in[8];
    const float* fc_w   = (const float*)d_in[9];
    const float* fc_b   = (const float*)d_in[10];
    const float* fc2_w  = (const float*)d_in[11];
    const float* fc2_b  = (const float*)d_in[12];
    float* out = (float*)d_out;

    __nv_bfloat16 *ahi, *alo, *bhi, *blo, *whi, *wlo;
    float *x1;
    cudaGetSymbolAddress((void**)&ahi, g_ahi);
    cudaGetSymbolAddress((void**)&alo, g_alo);
    cudaGetSymbolAddress((void**)&bhi, g_bhi);
    cudaGetSymbolAddress((void**)&blo, g_blo);
    cudaGetSymbolAddress((void**)&whi, g_whi);
    cudaGetSymbolAddress((void**)&wlo, g_wlo);
    cudaGetSymbolAddress((void**)&x1,  g_x1);

    static bool attr_set = false;
    if (!attr_set) {
        cudaFuncSetAttribute(gemm_tc<0>, cudaFuncAttributeMaxDynamicSharedMemorySize, GEMM_SMEM_BYTES);
        cudaFuncSetAttribute(gemm_tc<1>, cudaFuncAttributeMaxDynamicSharedMemorySize, GEMM_SMEM_BYTES);
        cudaFuncSetAttribute(gemm_tc<2>, cudaFuncAttributeMaxDynamicSharedMemorySize, GEMM_SMEM_BYTES);
        cudaFuncSetAttribute(gemm_tc<3>, cudaFuncAttributeMaxDynamicSharedMemorySize, GEMM_SMEM_BYTES);
        cudaFuncSetAttribute(attn_tc,    cudaFuncAttributeMaxDynamicSharedMemorySize, ATTN_SMEM);
        attr_set = true;
    }

    // 1. ln1 -> A pair
    ln_kernel<<<ROWS, 256>>>(x, ln1_w, ln1_b, ahi, alo);
    // 2. qkv = ln1 @ attn_w + attn_b -> bf16 pair (B buffers)
    wtrans_kernel<<<dim3(3 * D_MODEL / 32, D_MODEL / 32), 256>>>(attn_w, whi, wlo, D_MODEL, 3 * D_MODEL);
    gemm_tc<3><<<dim3(3 * D_MODEL / 128, ROWS / 256), 256, GEMM_SMEM_BYTES>>>(
        ahi, alo, whi, wlo, attn_b, nullptr, nullptr, bhi, blo,
        ROWS, 3 * D_MODEL, D_MODEL);
    // 3. attention -> y pair (A buffers)
    attn_tc<<<dim3(TT / 128, BB * N_HEAD), 128, ATTN_SMEM>>>(bhi, blo, ahi, alo);
    // 4. x1 = x + y @ proj_w + proj_b
    wtrans_kernel<<<dim3(D_MODEL / 32, D_MODEL / 32), 256>>>(proj_w, whi, wlo, D_MODEL, D_MODEL);
    gemm_tc<1><<<dim3(D_MODEL / 128, ROWS / 256), 256, GEMM_SMEM_BYTES>>>(
        ahi, alo, whi, wlo, proj_b, x, x1, nullptr, nullptr,
        ROWS, D_MODEL, D_MODEL);
    // 5. ln2 -> A pair
    ln_kernel<<<ROWS, 256>>>(x1, ln2_w, ln2_b, ahi, alo);
    // 6. h = gelu(ln2 @ fc_w + fc_b) -> B pair
    wtrans_kernel<<<dim3(EXPAND * D_MODEL / 32, D_MODEL / 32), 256>>>(fc_w, whi, wlo, D_MODEL, EXPAND * D_MODEL);
    gemm_tc<2><<<dim3(EXPAND * D_MODEL / 128, ROWS / 256), 256, GEMM_SMEM_BYTES>>>(
        ahi, alo, whi, wlo, fc_b, nullptr, nullptr, bhi, blo,
        ROWS, EXPAND * D_MODEL, D_MODEL);
    // 7. out = x1 + h @ fc2_w + fc2_b
    wtrans_kernel<<<dim3(D_MODEL / 32, EXPAND * D_MODEL / 32), 256>>>(fc2_w, whi, wlo, EXPAND * D_MODEL, D_MODEL);
    gemm_tc<1><<<dim3(D_MODEL / 128, ROWS / 256), 256, GEMM_SMEM_BYTES>>>(
        bhi, blo, whi, wlo, fc2_b, x1, out, nullptr, nullptr,
        ROWS, D_MODEL, EXPAND * D_MODEL);
}

// round 6
// speedup vs baseline: 1.0143x; 1.0143x over previous
#include <cuda_runtime.h>
#include <cuda_bf16.h>
#include <math.h>
#include <stdint.h>

#define D_MODEL 1024
#define N_HEAD  16
#define BB      2
#define TT      2048
#define ROWS    (BB*TT)      // 4096
#define EXPAND  4

// ---------------- scratch (device globals; no allocation allowed) ----------
__device__ __nv_bfloat16 g_ahi[ROWS * D_MODEL];
__device__ __nv_bfloat16 g_alo[ROWS * D_MODEL];
__device__ __nv_bfloat16 g_bhi[ROWS * EXPAND * D_MODEL];   // also holds qkv pair
__device__ __nv_bfloat16 g_blo[ROWS * EXPAND * D_MODEL];
__device__ __nv_bfloat16 g_whi[EXPAND * D_MODEL * D_MODEL];
__device__ __nv_bfloat16 g_wlo[EXPAND * D_MODEL * D_MODEL];
__device__ float g_x1 [ROWS * D_MODEL];

// ================= helpers ==================================================
__device__ __forceinline__ uint32_t smem_to_u32(const void* p) {
    uint32_t a;
    asm("{ .reg .u64 t; cvta.to.shared.u64 t, %1; cvt.u32.u64 %0, t; }" : "=r"(a) : "l"(p));
    return a;
}
#define SMEM_SWIZZLE_128B(off) ((off) ^ (((off) >> 3) & 0x70))
#define SMEM_SWIZZLE_64B(off)  ((off) ^ (((off) >> 3) & 0x30))

#define CP_ASYNC16(dst_u32, src_ptr) \
    asm volatile("cp.async.cg.shared.global [%0], [%1], 16;" :: "r"(dst_u32), "l"(src_ptr))
#define CP_COMMIT() asm volatile("cp.async.commit_group;" ::: "memory")
#define CP_WAIT0()  asm volatile("cp.async.wait_group 0;" ::: "memory")
#define CP_WAIT1()  asm volatile("cp.async.wait_group 1;" ::: "memory")

#define LDMATRIX_X4(r0, r1, r2, r3, addr) \
    asm volatile("ldmatrix.sync.aligned.m8n8.x4.shared.b16 {%0,%1,%2,%3}, [%4];" \
        : "=r"(r0), "=r"(r1), "=r"(r2), "=r"(r3) : "r"(addr))
#define LDMATRIX_X4_TRANS(r0, r1, r2, r3, addr) \
    asm volatile("ldmatrix.sync.aligned.m8n8.x4.trans.shared.b16 {%0,%1,%2,%3}, [%4];" \
        : "=r"(r0), "=r"(r1), "=r"(r2), "=r"(r3) : "r"(addr))

__device__ __forceinline__ void hmma(float* c, const uint32_t* a, const uint32_t* b) {
    asm volatile(
        "mma.sync.aligned.m16n8k16.row.col.f32.bf16.bf16.f32 "
        "{%0,%1,%2,%3}, {%4,%5,%6,%7}, {%8,%9}, {%0,%1,%2,%3};"
        : "+f"(c[0]), "+f"(c[1]), "+f"(c[2]), "+f"(c[3])
        : "r"(a[0]), "r"(a[1]), "r"(a[2]), "r"(a[3]), "r"(b[0]), "r"(b[1]));
}

__device__ __forceinline__ void split_bf16(float v, __nv_bfloat16& hi, __nv_bfloat16& lo) {
    hi = __float2bfloat16(v);
    lo = __float2bfloat16(v - __bfloat162float(hi));
}

// ---------------- LayerNorm -> bf16 hi/lo pair -------------------------------
__global__ __launch_bounds__(256)
void ln_kernel(const float* __restrict__ x, const float* __restrict__ w,
               const float* __restrict__ b,
               __nv_bfloat16* __restrict__ ohi, __nv_bfloat16* __restrict__ olo) {
    int row = blockIdx.x;
    const float4* xr = (const float4*)(x + (size_t)row * D_MODEL);
    float4 v = xr[threadIdx.x];
    float s  = v.x + v.y + v.z + v.w;
    float ss = v.x*v.x + v.y*v.y + v.z*v.z + v.w*v.w;
    #pragma unroll
    for (int o = 16; o; o >>= 1) {
        s  += __shfl_down_sync(0xffffffffu, s,  o);
        ss += __shfl_down_sync(0xffffffffu, ss, o);
    }
    __shared__ float rs[8], rss[8];
    __shared__ float mu_s, rstd_s;
    int wid = threadIdx.x >> 5, lid = threadIdx.x & 31;
    if (lid == 0) { rs[wid] = s; rss[wid] = ss; }
    __syncthreads();
    if (threadIdx.x == 0) {
        float ts = 0.f, tss = 0.f;
        #pragma unroll
        for (int i = 0; i < 8; i++) { ts += rs[i]; tss += rss[i]; }
        float mu  = ts * (1.0f / D_MODEL);
        float var = tss * (1.0f / D_MODEL) - mu * mu;
        mu_s = mu; rstd_s = rsqrtf(var + 1e-5f);
    }
    __syncthreads();
    float mu = mu_s, rstd = rstd_s;
    float4 wv = ((const float4*)w)[threadIdx.x];
    float4 bv = ((const float4*)b)[threadIdx.x];
    float o0 = (v.x - mu) * rstd * wv.x + bv.x;
    float o1 = (v.y - mu) * rstd * wv.y + bv.y;
    float o2 = (v.z - mu) * rstd * wv.z + bv.z;
    float o3 = (v.w - mu) * rstd * wv.w + bv.w;
    size_t base = (size_t)row * D_MODEL + threadIdx.x * 4;
    __nv_bfloat16 h, l;
    split_bf16(o0, h, l); ohi[base+0] = h; olo[base+0] = l;
    split_bf16(o1, h, l); ohi[base+1] = h; olo[base+1] = l;
    split_bf16(o2, h, l); ohi[base+2] = h; olo[base+2] = l;
    split_bf16(o3, h, l); ohi[base+3] = h; olo[base+3] = l;
}

// ---------------- weight transpose + split: W[K,N] -> Wt[N,K] ---------------
__global__ __launch_bounds__(256)
void wtrans_kernel(const float* __restrict__ W,
                   __nv_bfloat16* __restrict__ whi, __nv_bfloat16* __restrict__ wlo,
                   int K, int N) {
    __shared__ float t[32][33];
    int n0 = blockIdx.x * 32, k0 = blockIdx.y * 32;
    int tx = threadIdx.x & 31, ty = threadIdx.x >> 5;
    #pragma unroll
    for (int i = 0; i < 32; i += 8)
        t[ty + i][tx] = W[(size_t)(k0 + ty + i) * N + n0 + tx];
    __syncthreads();
    #pragma unroll
    for (int i = 0; i < 32; i += 8) {
        float v = t[tx][ty + i];
        __nv_bfloat16 h, l;
        split_bf16(v, h, l);
        size_t o = (size_t)(n0 + ty + i) * K + k0 + tx;
        whi[o] = h; wlo[o] = l;
    }
}

// ---------------- bf16x3 HMMA GEMM: C = (Ahi+Alo) @ (Bhi+Blo)^T -------------
// CTA tile 128x128, BK=32 (SW64), 3-stage cp.async ring, 2 CTAs/SM.
// 8 warps as 2(M) x 4(N), warp tile 64x32.
// EPI: 0 bias -> f32 C; 1 bias+residual -> f32 C; 2 bias+GELU -> bf16 pair;
//      3 bias -> bf16 pair
#define GEMM_STAGE_BYTES 32768           // AH 8K | AL 8K | BH 8K | BL 8K
#define GEMM_NSTAGE 3
#define GEMM_SMEM_BYTES (GEMM_NSTAGE * GEMM_STAGE_BYTES)

template<int EPI>
__global__ __launch_bounds__(256, 2)
void gemm_tc(const __nv_bfloat16* __restrict__ Ahi, const __nv_bfloat16* __restrict__ Alo,
             const __nv_bfloat16* __restrict__ Bhi, const __nv_bfloat16* __restrict__ Blo,
             const float* __restrict__ bias, const float* __restrict__ res,
             float* __restrict__ C,
             __nv_bfloat16* __restrict__ Chi, __nv_bfloat16* __restrict__ Clo,
             int M, int N, int K) {
    extern __shared__ __align__(128) char smem[];
    uint32_t su = smem_to_u32(smem);

    const int tid  = threadIdx.x;
    const int lane = tid & 31;
    const int wid  = tid >> 5;
    const int wm   = (wid & 1) * 64;    // 2 warps along M
    const int wn   = (wid >> 1) * 32;   // 4 warps along N
    const int m0 = blockIdx.y * 128, n0 = blockIdx.x * 128;

    float acc[4][4][4];
    #pragma unroll
    for (int i = 0; i < 4; i++)
        #pragma unroll
        for (int j = 0; j < 4; j++)
            #pragma unroll
            for (int k = 0; k < 4; k++) acc[i][j][k] = 0.f;

    const int nkt = K >> 5;              // K / 32
    const int lrow16 = lane & 15;
    const int khalf  = (lane >> 4) << 4; // 0 / 16 bytes

    // per-thread load slots: 2 x 16B per sub-buffer (512 chunks / 256 threads)
    const int e0 = tid, e1 = 256 + tid;
    const int r0_ = e0 >> 2, c0_ = (e0 & 3);
    const int r1_ = e1 >> 2, c1_ = (e1 & 3);
    const uint32_t d0 = SMEM_SWIZZLE_64B((uint32_t)(r0_ * 64 + c0_ * 16));
    const uint32_t d1 = SMEM_SWIZZLE_64B((uint32_t)(r1_ * 64 + c1_ * 16));

    auto issue_loads = [&](int kt) {
        uint32_t base = su + (kt % GEMM_NSTAGE) * GEMM_STAGE_BYTES;
        int k0 = kt << 5;
        size_t a0 = (size_t)(m0 + r0_) * K + k0 + c0_ * 8;
        size_t a1 = (size_t)(m0 + r1_) * K + k0 + c1_ * 8;
        size_t b0 = (size_t)(n0 + r0_) * K + k0 + c0_ * 8;
        size_t b1 = (size_t)(n0 + r1_) * K + k0 + c1_ * 8;
        CP_ASYNC16(base +         d0, Ahi + a0);
        CP_ASYNC16(base +         d1, Ahi + a1);
        CP_ASYNC16(base +  8192 + d0, Alo + a0);
        CP_ASYNC16(base +  8192 + d1, Alo + a1);
        CP_ASYNC16(base + 16384 + d0, Bhi + b0);
        CP_ASYNC16(base + 16384 + d1, Bhi + b1);
        CP_ASYNC16(base + 24576 + d0, Blo + b0);
        CP_ASYNC16(base + 24576 + d1, Blo + b1);
        CP_COMMIT();
    };

    issue_loads(0);
    if (nkt > 1) issue_loads(1);

    for (int kt = 0; kt < nkt; kt++) {
        if (kt + 1 < nkt) { CP_WAIT1(); } else { CP_WAIT0(); }
        __syncthreads();
        if (kt + 2 < nkt) issue_loads(kt + 2);

        uint32_t base = su + (kt % GEMM_NSTAGE) * GEMM_STAGE_BYTES;
        #pragma unroll
        for (int ks = 0; ks < 2; ks++) {
            const uint32_t kb = (uint32_t)(ks * 32 + khalf);
            // B fragments for this ks (4 n8 tiles, hi+lo)
            uint32_t bh[4][2], bl[4][2];
            #pragma unroll
            for (int p = 0; p < 2; p++) {
                int r = wn + p * 16 + lrow16;
                uint32_t off = (uint32_t)(r * 64) + (kb ^ (uint32_t)((r & 6) << 3));
                uint32_t t0, t1, t2, t3;
                LDMATRIX_X4(t0, t1, t2, t3, base + 16384 + off);
                bh[p*2][0] = t0; bh[p*2][1] = t2;
                bh[p*2+1][0] = t1; bh[p*2+1][1] = t3;
                LDMATRIX_X4(t0, t1, t2, t3, base + 24576 + off);
                bl[p*2][0] = t0; bl[p*2][1] = t2;
                bl[p*2+1][0] = t1; bl[p*2+1][1] = t3;
            }
            #pragma unroll
            for (int mt = 0; mt < 4; mt++) {
                int r = wm + mt * 16 + lrow16;
                uint32_t off = (uint32_t)(r * 64) + (kb ^ (uint32_t)((r & 6) << 3));
                uint32_t ah[4], al[4];
                LDMATRIX_X4(ah[0], ah[1], ah[2], ah[3], base + off);
                LDMATRIX_X4(al[0], al[1], al[2], al[3], base + 8192 + off);
                #pragma unroll
                for (int nt = 0; nt < 4; nt++) {
                    hmma(acc[mt][nt], ah, bh[nt]);
                    hmma(acc[mt][nt], ah, bl[nt]);
                    hmma(acc[mt][nt], al, bh[nt]);
                }
            }
        }
    }

    const int rbase = m0 + wm + (lane >> 2);
    const int cbase = n0 + wn + (lane & 3) * 2;
    #pragma unroll
    for (int mt = 0; mt < 4; mt++) {
        #pragma unroll
        for (int nt = 0; nt < 4; nt++) {
            int col = cbase + nt * 8;
            float b0 = bias[col], b1 = bias[col + 1];
            #pragma unroll
            for (int half = 0; half < 2; half++) {
                int row = rbase + mt * 16 + half * 8;
                float v0 = acc[mt][nt][half * 2]     + b0;
                float v1 = acc[mt][nt][half * 2 + 1] + b1;
                if (EPI == 1) {
                    float2 rv = *(const float2*)(res + (size_t)row * N + col);
                    v0 += rv.x; v1 += rv.y;
                }
                if (EPI == 2) {
                    v0 = 0.5f * v0 * (1.0f + erff(v0 * 0.70710678118654752f));
                    v1 = 0.5f * v1 * (1.0f + erff(v1 * 0.70710678118654752f));
                }
                if (EPI >= 2) {
                    __nv_bfloat16 h0, l0, h1, l1;
                    split_bf16(v0, h0, l0);
                    split_bf16(v1, h1, l1);
                    __nv_bfloat162 hp; hp.x = h0; hp.y = h1;
                    __nv_bfloat162 lp; lp.x = l0; lp.y = l1;
                    *(__nv_bfloat162*)(Chi + (size_t)row * N + col) = hp;
                    *(__nv_bfloat162*)(Clo + (size_t)row * N + col) = lp;
                } else {
                    float2 o; o.x = v0; o.y = v1;
                    *(float2*)(C + (size_t)row * N + col) = o;
                }
            }
        }
    }
}

// ---------------- tensor-core flash attention --------------------------------
#define ATTN_SMEM (32768 + 2 * 32768)   // Q pair + 2 KV stages

__global__ __launch_bounds__(128, 1)
void attn_tc(const __nv_bfloat16* __restrict__ qh, const __nv_bfloat16* __restrict__ ql,
             __nv_bfloat16* __restrict__ yhi, __nv_bfloat16* __restrict__ ylo) {
    extern __shared__ __align__(128) char smem[];
    uint32_t su = smem_to_u32(smem);
    const int tid = threadIdx.x, lane = tid & 31, w = tid >> 5;
    const int bh = blockIdx.y, b = bh >> 4, h = bh & 15;
    const int qt = (int)gridDim.x - 1 - (int)blockIdx.x;
    const int ntiles = qt * 2 + 2;

    const uint32_t QH = su, QL = su + 16384;
    const size_t qrow0 = (size_t)(b * TT + qt * 128);

    #pragma unroll
    for (int j = 0; j < 8; j++) {
        int e = j * 128 + tid; int r = e >> 3, c = e & 7;
        uint32_t d = SMEM_SWIZZLE_128B((uint32_t)(r * 128 + c * 16));
        size_t src = (qrow0 + r) * (3 * D_MODEL) + h * 64 + c * 8;
        CP_ASYNC16(QH + d, qh + src);
        CP_ASYNC16(QL + d, ql + src);
    }
    auto issue_kv = [&](int kt, int s) {
        uint32_t base = su + 32768 + s * 32768;
        size_t krow0 = (size_t)(b * TT + kt * 64);
        #pragma unroll
        for (int j = 0; j < 4; j++) {
            int e = j * 128 + tid; int r = e >> 3, c = e & 7;
            uint32_t d = SMEM_SWIZZLE_128B((uint32_t)(r * 128 + c * 16));
            size_t ksrc = (krow0 + r) * (3 * D_MODEL) + D_MODEL + h * 64 + c * 8;
            size_t vsrc = ksrc + D_MODEL;
            CP_ASYNC16(base +         d, qh + ksrc);
            CP_ASYNC16(base +  8192 + d, ql + ksrc);
            CP_ASYNC16(base + 16384 + d, qh + vsrc);
            CP_ASYNC16(base + 24576 + d, ql + vsrc);
        }
        CP_COMMIT();
    };
    issue_kv(0, 0);

    float O[2][8][4];
    #pragma unroll
    for (int mt = 0; mt < 2; mt++)
        #pragma unroll
        for (int dt = 0; dt < 8; dt++)
            #pragma unroll
            for (int k = 0; k < 4; k++) O[mt][dt][k] = 0.f;
    float mrow[2][2] = {{-1e30f, -1e30f}, {-1e30f, -1e30f}};
    float lrow[2][2] = {{0.f, 0.f}, {0.f, 0.f}};

    const int lrow16 = lane & 15;
    const uint32_t khalfB = (uint32_t)((lane >> 4) << 4);
    const int r4 = lane >> 2, c2 = (lane & 3) * 2;

    for (int kt = 0; kt < ntiles; kt++) {
        int s = kt & 1;
        if (kt + 1 < ntiles) { issue_kv(kt + 1, s ^ 1); CP_WAIT1(); }
        else                 { CP_WAIT0(); }
        __syncthreads();
        const uint32_t KB = su + 32768 + s * 32768;
        const uint32_t VB = KB + 16384;

        #pragma unroll
        for (int mt = 0; mt < 2; mt++) {
            const int qmt = qt * 128 + w * 32 + mt * 16;
            float sa[8][4];
            #pragma unroll
            for (int nt = 0; nt < 8; nt++)
                #pragma unroll
                for (int k = 0; k < 4; k++) sa[nt][k] = 0.f;

            #pragma unroll
            for (int ks = 0; ks < 4; ks++) {
                const uint32_t kb = (uint32_t)(ks * 32) + khalfB;
                const int ar = w * 32 + mt * 16 + lrow16;
                uint32_t aoff = (uint32_t)(ar * 128) + (kb ^ (uint32_t)((ar & 7) << 4));
                uint32_t ah[4], al[4];
                LDMATRIX_X4(ah[0], ah[1], ah[2], ah[3], QH + aoff);
                LDMATRIX_X4(al[0], al[1], al[2], al[3], QL + aoff);
                uint32_t kh[8][2], kl[8][2];
                #pragma unroll
                for (int p = 0; p < 4; p++) {
                    const int br = p * 16 + lrow16;
                    uint32_t boff = (uint32_t)(br * 128) + (kb ^ (uint32_t)((br & 7) << 4));
                    uint32_t t0, t1, t2, t3;
                    LDMATRIX_X4(t0, t1, t2, t3, KB + boff);
                    kh[p*2][0] = t0; kh[p*2][1] = t2;
                    kh[p*2+1][0] = t1; kh[p*2+1][1] = t3;
                    LDMATRIX_X4(t0, t1, t2, t3, KB + 8192 + boff);
                    kl[p*2][0] = t0; kl[p*2][1] = t2;
                    kl[p*2+1][0] = t1; kl[p*2+1][1] = t3;
                }
                #pragma unroll
                for (int nt = 0; nt < 8; nt++) {
                    hmma(sa[nt], ah, kh[nt]);
                    hmma(sa[nt], ah, kl[nt]);
                    hmma(sa[nt], al, kh[nt]);
                }
            }

            #pragma unroll
            for (int nt = 0; nt < 8; nt++)
                #pragma unroll
                for (int k = 0; k < 4; k++) sa[nt][k] *= 0.125f;

            const int q0 = qmt + r4;
            if (kt * 64 + 63 > qmt) {
                #pragma unroll
                for (int nt = 0; nt < 8; nt++) {
                    int kv0 = kt * 64 + nt * 8 + c2;
                    if (kv0     > q0)     sa[nt][0] = -1e30f;
                    if (kv0 + 1 > q0)     sa[nt][1] = -1e30f;
                    if (kv0     > q0 + 8) sa[nt][2] = -1e30f;
                    if (kv0 + 1 > q0 + 8) sa[nt][3] = -1e30f;
                }
            }

            float tm0 = -1e30f, tm1 = -1e30f;
            #pragma unroll
            for (int nt = 0; nt < 8; nt++) {
                tm0 = fmaxf(tm0, fmaxf(sa[nt][0], sa[nt][1]));
                tm1 = fmaxf(tm1, fmaxf(sa[nt][2], sa[nt][3]));
            }
            tm0 = fmaxf(tm0, __shfl_xor_sync(0xffffffffu, tm0, 1));
            tm0 = fmaxf(tm0, __shfl_xor_sync(0xffffffffu, tm0, 2));
            tm1 = fmaxf(tm1, __shfl_xor_sync(0xffffffffu, tm1, 1));
            tm1 = fmaxf(tm1, __shfl_xor_sync(0xffffffffu, tm1, 2));
            float nm0 = fmaxf(mrow[mt][0], tm0), nm1 = fmaxf(mrow[mt][1], tm1);
            float cor0 = __expf(mrow[mt][0] - nm0), cor1 = __expf(mrow[mt][1] - nm1);
            mrow[mt][0] = nm0; mrow[mt][1] = nm1;

            float ps0 = 0.f, ps1 = 0.f;
            uint32_t Ph[8][2], Pl[8][2];
            #pragma unroll
            for (int nt = 0; nt < 8; nt++) {
                float p00 = __expf(sa[nt][0] - nm0), p01 = __expf(sa[nt][1] - nm0);
                float p10 = __expf(sa[nt][2] - nm1), p11 = __expf(sa[nt][3] - nm1);
                ps0 += p00 + p01; ps1 += p10 + p11;
                __nv_bfloat16 h0, l0, h1, l1;
                split_bf16(p00, h0, l0); split_bf16(p01, h1, l1);
                Ph[nt][0] = ((uint32_t)*(uint16_t*)&h1 << 16) | *(uint16_t*)&h0;
                Pl[nt][0] = ((uint32_t)*(uint16_t*)&l1 << 16) | *(uint16_t*)&l0;
                split_bf16(p10, h0, l0); split_bf16(p11, h1, l1);
                Ph[nt][1] = ((uint32_t)*(uint16_t*)&h1 << 16) | *(uint16_t*)&h0;
                Pl[nt][1] = ((uint32_t)*(uint16_t*)&l1 << 16) | *(uint16_t*)&l0;
            }
            ps0 += __shfl_xor_sync(0xffffffffu, ps0, 1);
            ps0 += __shfl_xor_sync(0xffffffffu, ps0, 2);
            ps1 += __shfl_xor_sync(0xffffffffu, ps1, 1);
            ps1 += __shfl_xor_sync(0xffffffffu, ps1, 2);
            lrow[mt][0] = lrow[mt][0] * cor0 + ps0;
            lrow[mt][1] = lrow[mt][1] * cor1 + ps1;

            #pragma unroll
            for (int dt = 0; dt < 8; dt++) {
                O[mt][dt][0] *= cor0; O[mt][dt][1] *= cor0;
                O[mt][dt][2] *= cor1; O[mt][dt][3] *= cor1;
            }

            #pragma unroll
            for (int ks = 0; ks < 4; ks++) {
                uint32_t vh[8][2], vl[8][2];
                #pragma unroll
                for (int dc = 0; dc < 4; dc++) {
                    const int vr = ks * 16 + lrow16;
                    uint32_t voff = (uint32_t)(vr * 128) +
                        (((uint32_t)(dc * 32) + khalfB) ^ (uint32_t)((vr & 7) << 4));
                    uint32_t t0, t1, t2, t3;
                    LDMATRIX_X4_TRANS(t0, t1, t2, t3, VB + voff);
                    vh[dc*2][0] = t0; vh[dc*2][1] = t1;
                    vh[dc*2+1][0] = t2; vh[dc*2+1][1] = t3;
                    LDMATRIX_X4_TRANS(t0, t1, t2, t3, VB + 8192 + voff);
                    vl[dc*2][0] = t0; vl[dc*2][1] = t1;
                    vl[dc*2+1][0] = t2; vl[dc*2+1][1] = t3;
                }
                uint32_t aph[4] = {Ph[2*ks][0], Ph[2*ks][1], Ph[2*ks+1][0], Ph[2*ks+1][1]};
                uint32_t apl[4] = {Pl[2*ks][0], Pl[2*ks][1], Pl[2*ks+1][0], Pl[2*ks+1][1]};
                #pragma unroll
                for (int dt = 0; dt < 8; dt++) {
                    hmma(O[mt][dt], aph, vh[dt]);
                    hmma(O[mt][dt], apl, vh[dt]);
                    hmma(O[mt][dt], aph, vl[dt]);
                }
            }
        } // mt
        __syncthreads();
    } // kt

    #pragma unroll
    for (int mt = 0; mt < 2; mt++) {
        float inv0 = 1.0f / lrow[mt][0], inv1 = 1.0f / lrow[mt][1];
        size_t row0 = qrow0 + w * 32 + mt * 16 + r4;
        size_t row1 = row0 + 8;
        #pragma unroll
        for (int dt = 0; dt < 8; dt++) {
            int col = h * 64 + dt * 8 + c2;
            float v0 = O[mt][dt][0] * inv0, v1 = O[mt][dt][1] * inv0;
            float v2 = O[mt][dt][2] * inv1, v3 = O[mt][dt][3] * inv1;
            __nv_bfloat16 h0, l0, h1, l1;
            split_bf16(v0, h0, l0); split_bf16(v1, h1, l1);
            __nv_bfloat162 hp, lp;
            hp.x = h0; hp.y = h1; lp.x = l0; lp.y = l1;
            *(__nv_bfloat162*)(yhi + row0 * D_MODEL + col) = hp;
            *(__nv_bfloat162*)(ylo + row0 * D_MODEL + col) = lp;
            split_bf16(v2, h0, l0); split_bf16(v3, h1, l1);
            hp.x = h0; hp.y = h1; lp.x = l0; lp.y = l1;
            *(__nv_bfloat162*)(yhi + row1 * D_MODEL + col) = hp;
            *(__nv_bfloat162*)(ylo + row1 * D_MODEL + col) = lp;
        }
    }
}

// ---------------- launch ----------------------------------------------------
extern "C" void kernel_launch(void* const* d_in, const int* in_sizes, int n_in,
                              void* d_out, int out_size) {
    const float* x      = (const float*)d_in[0];
    const float* ln1_w  = (const float*)d_in[1];
    const float* ln1_b  = (const float*)d_in[2];
    const float* attn_w = (const float*)d_in[3];
    const float* attn_b = (const float*)d_in[4];
    const float* proj_w = (const float*)d_in[5];
    const float* proj_b = (const float*)d_in[6];
    const float* ln2_w  = (const float*)d_in[7];
    const float* ln2_b  = (const float*)d_in[8];
    const float* fc_w   = (const float*)d_in[9];
    const float* fc_b   = (const float*)d_in[10];
    const float* fc2_w  = (const float*)d_in[11];
    const float* fc2_b  = (const float*)d_in[12];
    float* out = (float*)d_out;

    __nv_bfloat16 *ahi, *alo, *bhi, *blo, *whi, *wlo;
    float *x1;
    cudaGetSymbolAddress((void**)&ahi, g_ahi);
    cudaGetSymbolAddress((void**)&alo, g_alo);
    cudaGetSymbolAddress((void**)&bhi, g_bhi);
    cudaGetSymbolAddress((void**)&blo, g_blo);
    cudaGetSymbolAddress((void**)&whi, g_whi);
    cudaGetSymbolAddress((void**)&wlo, g_wlo);
    cudaGetSymbolAddress((void**)&x1,  g_x1);

    static bool attr_set = false;
    if (!attr_set) {
        cudaFuncSetAttribute(gemm_tc<0>, cudaFuncAttributeMaxDynamicSharedMemorySize, GEMM_SMEM_BYTES);
        cudaFuncSetAttribute(gemm_tc<1>, cudaFuncAttributeMaxDynamicSharedMemorySize, GEMM_SMEM_BYTES);
        cudaFuncSetAttribute(gemm_tc<2>, cudaFuncAttributeMaxDynamicSharedMemorySize, GEMM_SMEM_BYTES);
        cudaFuncSetAttribute(gemm_tc<3>, cudaFuncAttributeMaxDynamicSharedMemorySize, GEMM_SMEM_BYTES);
        cudaFuncSetAttribute(attn_tc,    cudaFuncAttributeMaxDynamicSharedMemorySize, ATTN_SMEM);
        attr_set = true;
    }

    // 1. ln1 -> A pair
    ln_kernel<<<ROWS, 256>>>(x, ln1_w, ln1_b, ahi, alo);
    // 2. qkv = ln1 @ attn_w + attn_b -> bf16 pair (B buffers)
    wtrans_kernel<<<dim3(3 * D_MODEL / 32, D_MODEL / 32), 256>>>(attn_w, whi, wlo, D_MODEL, 3 * D_MODEL);
    gemm_tc<3><<<dim3(3 * D_MODEL / 128, ROWS / 128), 256, GEMM_SMEM_BYTES>>>(
        ahi, alo, whi, wlo, attn_b, nullptr, nullptr, bhi, blo,
        ROWS, 3 * D_MODEL, D_MODEL);
    // 3. attention -> y pair (A buffers)
    attn_tc<<<dim3(TT / 128, BB * N_HEAD), 128, ATTN_SMEM>>>(bhi, blo, ahi, alo);
    // 4. x1 = x + y @ proj_w + proj_b
    wtrans_kernel<<<dim3(D_MODEL / 32, D_MODEL / 32), 256>>>(proj_w, whi, wlo, D_MODEL, D_MODEL);
    gemm_tc<1><<<dim3(D_MODEL / 128, ROWS / 128), 256, GEMM_SMEM_BYTES>>>(
        ahi, alo, whi, wlo, proj_b, x, x1, nullptr, nullptr,
        ROWS, D_MODEL, D_MODEL);
    // 5. ln2 -> A pair
    ln_kernel<<<ROWS, 256>>>(x1, ln2_w, ln2_b, ahi, alo);
    // 6. h = gelu(ln2 @ fc_w + fc_b) -> B pair
    wtrans_kernel<<<dim3(EXPAND * D_MODEL / 32, D_MODEL / 32), 256>>>(fc_w, whi, wlo, D_MODEL, EXPAND * D_MODEL);
    gemm_tc<2><<<dim3(EXPAND * D_MODEL / 128, ROWS / 128), 256, GEMM_SMEM_BYTES>>>(
        ahi, alo, whi, wlo, fc_b, nullptr, nullptr, bhi, blo,
        ROWS, EXPAND * D_MODEL, D_MODEL);
    // 7. out = x1 + h @ fc2_w + fc2_b
    wtrans_kernel<<<dim3(D_MODEL / 32, EXPAND * D_MODEL / 32), 256>>>(fc2_w, whi, wlo, EXPAND * D_MODEL, D_MODEL);
    gemm_tc<1><<<dim3(D_MODEL / 128, ROWS / 128), 256, GEMM_SMEM_BYTES>>>(
        bhi, blo, whi, wlo, fc2_b, x1, out, nullptr, nullptr,
        ROWS, D_MODEL, EXPAND * D_MODEL);
}